// round 9
// baseline (speedup 1.0000x reference)
#include <cuda_runtime.h>
#include <math.h>
#include <float.h>

#define BATCH 8
#define NPTS  2048
#define MPTS  1024
#define KNN   32
#define NEGS  0.2f
#define ASCALE 0.08838834764831845f  /* 1/sqrt(128) */

// ------------------------------ device scratch ------------------------------
__device__ float d_S[(size_t)BATCH*NPTS*NPTS];          // Grams / attention S
__device__ float d_xp[BATCH*NPTS*3];
__device__ float d_sq[BATCH*NPTS];
__device__ int   d_idx[BATCH*NPTS*KNN];
__device__ float d_A [BATCH*NPTS*128];
__device__ float d_Bm[BATCH*NPTS*128];
__device__ float d_h [BATCH*NPTS*256];                  // [e0 | e1]
__device__ float d_q [BATCH*NPTS*128];
__device__ float d_k [BATCH*NPTS*128];
__device__ float d_v [BATCH*NPTS*128];
__device__ float d_o [BATCH*NPTS*128];
__device__ float d_y [BATCH*NPTS*128];
__device__ float d_f1[(size_t)BATCH*NPTS*512];
__device__ float d_ff[BATCH*NPTS*128];
__device__ float d_hf[BATCH*NPTS*128];                  // h_full
__device__ float d_hd [BATCH*MPTS*128];
__device__ float d_hd2[BATCH*MPTS*128];
__device__ float d_hu[BATCH*NPTS*128];
__device__ float d_xt[BATCH*NPTS*128];                  // x_tmp
__device__ float d_xh[(size_t)BATCH*NPTS*1024];
__device__ float d_xc[(size_t)BATCH*NPTS*1024];
__device__ float d_x3[BATCH*NPTS*256];
__device__ float d_ot[BATCH*NPTS*50];
__device__ float d_ps[(size_t)BATCH*NPTS*128];          // stat partial sums
__device__ float d_pq[(size_t)BATCH*NPTS*128];          // stat partial sumsq
__device__ float d_mu[1024];
__device__ float d_is[1024];
__device__ float d_wd[128*128];
__device__ float d_rm[BATCH*NPTS];
__device__ float d_ri[BATCH*NPTS];
__device__ float d_sc[BATCH*NPTS];
__device__ int   d_sel[BATCH*MPTS];
__device__ float d_g [BATCH*2112];
__device__ float d_gc[BATCH*1024];
__device__ float d_cid[BATCH*64];

// ------------------------------ GEMM (fp32 tiled) ---------------------------
// C[i,j] = sum_k A[i,k] * (transB ? B[j,k] : B[k,j]); rmode: 0 none,
// 1: += R[i*ldr+j] (with z-stride sR), 2: += R[(i>>11)*ldr+j] (per-batch row vec)
#define GBK 16
__global__ void gemm_kernel(const float* __restrict__ A, const float* __restrict__ B,
                            float* __restrict__ C, const float* __restrict__ R,
                            int M, int N, int Kd, int lda, int ldb, int ldc, int ldr,
                            long sA, long sB, long sC, long sR, int transB, int rmode)
{
    __shared__ float As[GBK][64];
    __shared__ float Bs[GBK][64];
    int bz = blockIdx.z;
    A += (size_t)bz * sA; B += (size_t)bz * sB; C += (size_t)bz * sC;
    if (R && rmode == 1) R += (size_t)bz * sR;
    int bm = blockIdx.y * 64, bn = blockIdx.x * 64;
    int tid = threadIdx.x;
    int tm = (tid >> 4) << 2;
    int tn = (tid & 15) << 2;
    float acc[4][4];
#pragma unroll
    for (int i = 0; i < 4; i++)
#pragma unroll
        for (int j = 0; j < 4; j++) acc[i][j] = 0.f;

    for (int k0 = 0; k0 < Kd; k0 += GBK) {
#pragma unroll
        for (int i = 0; i < 4; i++) {
            int idx = tid + i * 256;
            int m = idx >> 4, kk = idx & 15;
            int gm = bm + m, gk = k0 + kk;
            As[kk][m] = (gm < M && gk < Kd) ? A[(size_t)gm * lda + gk] : 0.f;
        }
        if (transB) {
#pragma unroll
            for (int i = 0; i < 4; i++) {
                int idx = tid + i * 256;
                int n = idx >> 4, kk = idx & 15;
                int gn = bn + n, gk = k0 + kk;
                Bs[kk][n] = (gn < N && gk < Kd) ? B[(size_t)gn * ldb + gk] : 0.f;
            }
        } else {
#pragma unroll
            for (int i = 0; i < 4; i++) {
                int idx = tid + i * 256;
                int kk = idx >> 6, n = idx & 63;
                int gn = bn + n, gk = k0 + kk;
                Bs[kk][n] = (gn < N && gk < Kd) ? B[(size_t)gk * ldb + gn] : 0.f;
            }
        }
        __syncthreads();
#pragma unroll
        for (int kk = 0; kk < GBK; kk++) {
            float a0 = As[kk][tm], a1 = As[kk][tm+1], a2 = As[kk][tm+2], a3 = As[kk][tm+3];
            float b0 = Bs[kk][tn], b1 = Bs[kk][tn+1], b2 = Bs[kk][tn+2], b3 = Bs[kk][tn+3];
            acc[0][0]+=a0*b0; acc[0][1]+=a0*b1; acc[0][2]+=a0*b2; acc[0][3]+=a0*b3;
            acc[1][0]+=a1*b0; acc[1][1]+=a1*b1; acc[1][2]+=a1*b2; acc[1][3]+=a1*b3;
            acc[2][0]+=a2*b0; acc[2][1]+=a2*b1; acc[2][2]+=a2*b2; acc[2][3]+=a2*b3;
            acc[3][0]+=a3*b0; acc[3][1]+=a3*b1; acc[3][2]+=a3*b2; acc[3][3]+=a3*b3;
        }
        __syncthreads();
    }
#pragma unroll
    for (int i = 0; i < 4; i++) {
        int gm = bm + tm + i;
        if (gm >= M) continue;
#pragma unroll
        for (int j = 0; j < 4; j++) {
            int gn = bn + tn + j;
            if (gn >= N) continue;
            float vv = acc[i][j];
            if (rmode == 1) vv += R[(size_t)gm * ldr + gn];
            else if (rmode == 2) vv += R[(size_t)(gm >> 11) * ldr + gn];
            C[(size_t)gm * ldc + gn] = vv;
        }
    }
}

// --------------------------- misc small kernels -----------------------------
__global__ void tin_kernel(const float* __restrict__ x, float* __restrict__ xp)
{
    int e = blockIdx.x * blockDim.x + threadIdx.x;
    if (e >= BATCH * NPTS * 3) return;
    int b = e / (NPTS * 3), r = e % (NPTS * 3);
    int n = r / 3, c = r % 3;
    xp[e] = x[(size_t)b * 3 * NPTS + (size_t)c * NPTS + n];
}

__global__ void tout_kernel(const float* __restrict__ t, float* __restrict__ out)
{
    int e = blockIdx.x * blockDim.x + threadIdx.x;
    if (e >= BATCH * 50 * NPTS) return;
    int b = e / (50 * NPTS), r = e % (50 * NPTS);
    int o = r / NPTS, n = r % NPTS;
    out[e] = t[((size_t)b * NPTS + n) * 50 + o];
}

__global__ void wdiff_kernel(const float* __restrict__ W, float* __restrict__ wd,
                             int Cout, int Cin, int ldw)
{
    int e = blockIdx.x * blockDim.x + threadIdx.x;
    if (e >= Cout * Cin) return;
    int o = e / Cin, c = e % Cin;
    wd[e] = W[o * ldw + c] - W[o * ldw + Cin + c];
}

__global__ void rowsumsq_kernel(const float* __restrict__ X, int ldx, int C,
                                long rows, float* __restrict__ sq)
{
    long r = (long)blockIdx.x * blockDim.x + threadIdx.x;
    if (r >= rows) return;
    const float* p = X + (size_t)r * ldx;
    float s = 0.f;
    for (int c = 0; c < C; c++) s += p[c] * p[c];
    sq[r] = s;
}

// --------------------------------- knn select -------------------------------
__global__ void knn_select_kernel(const float* __restrict__ inner, const float* __restrict__ sq,
                                  int Np, int* __restrict__ idxOut)
{
    __shared__ float sval[2048];
    __shared__ float cmin[128];
    __shared__ int   cidx[128];
    __shared__ int   ssel;
    int b = blockIdx.y, n = blockIdx.x, t = threadIdx.x;
    const float* row = inner + ((size_t)b * Np + n) * (size_t)Np;
    const float* sqb = sq + (size_t)b * Np;
    float sqn = sqb[n];
    for (int m = t; m < Np; m += 128) sval[m] = sqn - 2.f * row[m] + sqb[m];
    __syncthreads();
    int chunk = Np >> 7;
    int base = t * chunk;
    float lmin = FLT_MAX; int lidx = base;
    for (int i = 0; i < chunk; i++) { float v = sval[base + i]; if (v < lmin) { lmin = v; lidx = base + i; } }
    int* orow = idxOut + ((size_t)b * Np + n) * KNN;
    for (int s = 0; s < KNN; s++) {
        cmin[t] = lmin; cidx[t] = lidx;
        __syncthreads();
        for (int off = 64; off > 0; off >>= 1) {
            if (t < off) {
                float v2 = cmin[t + off]; int i2 = cidx[t + off];
                if (v2 < cmin[t] || (v2 == cmin[t] && i2 < cidx[t])) { cmin[t] = v2; cidx[t] = i2; }
            }
            __syncthreads();
        }
        if (t == 0) { orow[s] = cidx[0]; ssel = cidx[0]; }
        __syncthreads();
        int sel = ssel;
        if (sel >= base && sel < base + chunk) {
            sval[sel] = FLT_MAX;
            lmin = FLT_MAX; lidx = base;
            for (int i = 0; i < chunk; i++) { float v = sval[base + i]; if (v < lmin) { lmin = v; lidx = base + i; } }
        }
        __syncthreads();
    }
}

// -------------------------- edge-conv gather+max+stats ----------------------
__global__ void edge_gather_kernel(const float* __restrict__ At, const float* __restrict__ Bt,
                                   const int* __restrict__ idx, float* __restrict__ out, int ldo,
                                   float* __restrict__ ps, float* __restrict__ pq, int Np)
{
    __shared__ int sidx[KNN];
    int b = blockIdx.y, n = blockIdx.x, t = threadIdx.x;
    size_t pbase = (size_t)b * Np + n;
    if (t < KNN) sidx[t] = idx[pbase * KNN + t];
    __syncthreads();
    float a = At[pbase * 128 + t];
    float s = 0.f, q = 0.f, mx = -FLT_MAX;
#pragma unroll
    for (int k = 0; k < KNN; k++) {
        float v = a + Bt[((size_t)b * Np + sidx[k]) * 128 + t];
        s += v; q += v * v; mx = fmaxf(mx, v);
    }
    out[pbase * ldo + t] = mx;
    ps[pbase * 128 + t] = s;
    pq[pbase * 128 + t] = q;
}

// ------------------------------ batch-norm pieces ---------------------------
__global__ void colstats_kernel(const float* __restrict__ X, int ldx, long rows, int C,
                                float* __restrict__ ps, float* __restrict__ pq)
{
    int blk = blockIdx.x, t = threadIdx.x;
    long r0 = (long)blk * 64;
    long r1 = r0 + 64; if (r1 > rows) r1 = rows;
    for (int c = t; c < C; c += 256) {
        float s = 0.f, q = 0.f;
        for (long r = r0; r < r1; r++) { float v = X[(size_t)r * ldx + c]; s += v; q += v * v; }
        ps[(size_t)blk * C + c] = s;
        pq[(size_t)blk * C + c] = q;
    }
}

__global__ void reduce_stats_kernel(const float* __restrict__ ps, const float* __restrict__ pq,
                                    int nblk, int C, float cntInv,
                                    float* __restrict__ mu, float* __restrict__ istd)
{
    __shared__ float rs[256], rq[256];
    int c = blockIdx.x, t = threadIdx.x;
    float s = 0.f, q = 0.f;
    for (int i = t; i < nblk; i += 256) { s += ps[(size_t)i * C + c]; q += pq[(size_t)i * C + c]; }
    rs[t] = s; rq[t] = q;
    __syncthreads();
    for (int off = 128; off > 0; off >>= 1) {
        if (t < off) { rs[t] += rs[t + off]; rq[t] += rq[t + off]; }
        __syncthreads();
    }
    if (t == 0) {
        float m = rs[0] * cntInv;
        float var = rq[0] * cntInv - m * m;
        mu[c] = m;
        istd[c] = rsqrtf(var + 1e-5f);
    }
}

__global__ void bn_leaky_kernel(const float* __restrict__ X, int ldx, float* __restrict__ Y, int ldy,
                                const float* __restrict__ R, int ldr,
                                const float* __restrict__ mu, const float* __restrict__ istd,
                                long rows, int C)
{
    long e = (long)blockIdx.x * blockDim.x + threadIdx.x;
    if (e >= rows * (long)C) return;
    long r = e / C; int c = (int)(e % C);
    float v = (X[(size_t)r * ldx + c] - mu[c]) * istd[c];
    v = v >= 0.f ? v : NEGS * v;
    if (R) v += R[(size_t)r * ldr + c];
    Y[(size_t)r * ldy + c] = v;
}

// ------------------------------ local knn attention -------------------------
__global__ void attn_kernel(const float* __restrict__ Q, const float* __restrict__ Kf,
                            const float* __restrict__ Vf, const int* __restrict__ idx,
                            float* __restrict__ O, int Np)
{
    __shared__ float qs[128];
    __shared__ float Ks[32 * 129];
    __shared__ int   sidx[KNN];
    __shared__ float sa[KNN];
    int b = blockIdx.y, n = blockIdx.x, t = threadIdx.x;
    size_t pbase = (size_t)b * Np + n;
    qs[t] = Q[pbase * 128 + t];
    if (t < KNN) sidx[t] = idx[pbase * KNN + t];
    __syncthreads();
    for (int e = t; e < KNN * 128; e += 128) {
        int k = e >> 7, c = e & 127;
        Ks[k * 129 + c] = Kf[((size_t)b * Np + sidx[k]) * 128 + c];
    }
    __syncthreads();
    if (t < KNN) {
        float dv = 0.f;
        for (int c = 0; c < 128; c++) dv += qs[c] * Ks[t * 129 + c];
        dv *= ASCALE;
        float mx = dv;
        for (int off = 16; off; off >>= 1) mx = fmaxf(mx, __shfl_xor_sync(0xffffffffu, mx, off));
        float ee = expf(dv - mx);
        float sm = ee;
        for (int off = 16; off; off >>= 1) sm += __shfl_xor_sync(0xffffffffu, sm, off);
        sa[t] = ee / sm;
    }
    __syncthreads();
    float acc = 0.f;
#pragma unroll
    for (int k = 0; k < KNN; k++) acc += sa[k] * Vf[((size_t)b * Np + sidx[k]) * 128 + t];
    O[pbase * 128 + t] = acc;
}

// ------------------------------ down_global pieces --------------------------
__global__ void rowstats_kernel(const float* __restrict__ S, int Np,
                                float* __restrict__ rmax, float* __restrict__ rsinv)
{
    __shared__ float red[256];
    int b = blockIdx.y, n = blockIdx.x, t = threadIdx.x;
    const float* row = S + ((size_t)b * Np + n) * (size_t)Np;
    float mx = -FLT_MAX;
    for (int m = t; m < Np; m += 256) mx = fmaxf(mx, row[m] * ASCALE);
    red[t] = mx;
    __syncthreads();
    for (int off = 128; off > 0; off >>= 1) { if (t < off) red[t] = fmaxf(red[t], red[t + off]); __syncthreads(); }
    float g = red[0];
    __syncthreads();
    float s = 0.f;
    for (int m = t; m < Np; m += 256) s += expf(row[m] * ASCALE - g);
    red[t] = s;
    __syncthreads();
    for (int off = 128; off > 0; off >>= 1) { if (t < off) red[t] += red[t + off]; __syncthreads(); }
    if (t == 0) { rmax[b * Np + n] = g; rsinv[b * Np + n] = 1.f / red[0]; }
}

__global__ void colscore_kernel(const float* __restrict__ S, int Np,
                                const float* __restrict__ rmax, const float* __restrict__ rsinv,
                                float* __restrict__ score)
{
    int b = blockIdx.y;
    int m = blockIdx.x * 128 + threadIdx.x;
    const float* Sb = S + (size_t)b * Np * Np;
    const float* rm = rmax + b * Np;
    const float* ri = rsinv + b * Np;
    float acc = 0.f;
    for (int n = 0; n < Np; n++) acc += expf(Sb[(size_t)n * Np + m] * ASCALE - rm[n]) * ri[n];
    score[b * Np + m] = acc / (float)Np;
}

__global__ void topm_kernel(const float* __restrict__ score, int* __restrict__ sel)
{
    __shared__ float sv[2048];
    __shared__ int   si[2048];
    int b = blockIdx.x, t = threadIdx.x;
    for (int i = t; i < 2048; i += 1024) { sv[i] = score[b * 2048 + i]; si[i] = i; }
    __syncthreads();
    for (int k = 2; k <= 2048; k <<= 1) {
        for (int j = k >> 1; j > 0; j >>= 1) {
            for (int w = t; w < 2048; w += 1024) {
                int ixj = w ^ j;
                if (ixj > w) {
                    bool dir = ((w & k) == 0);
                    float va = sv[w], vb = sv[ixj];
                    int ia = si[w], ib = si[ixj];
                    bool bBetter = (vb > va) || (vb == va && ib < ia);
                    if (bBetter == dir) { sv[w] = vb; si[w] = ib; sv[ixj] = va; si[ixj] = ia; }
                }
            }
            __syncthreads();
        }
    }
    for (int i = t; i < 1024; i += 1024) sel[b * 1024 + i] = si[i];
}

__global__ void gather_rows_kernel(const float* __restrict__ X, const int* __restrict__ sel,
                                   float* __restrict__ Y)
{
    int b = blockIdx.y, j = blockIdx.x, t = threadIdx.x;
    Y[((size_t)b * MPTS + j) * 128 + t] = X[((size_t)b * NPTS + sel[b * MPTS + j]) * 128 + t];
}

// -------------------------------- up softmax --------------------------------
__global__ void row_softmax_kernel(float* __restrict__ S, int cols, float scale)
{
    __shared__ float red[256];
    size_t base = (size_t)blockIdx.x * cols;
    int t = threadIdx.x;
    float mx = -FLT_MAX;
    for (int j = t; j < cols; j += 256) mx = fmaxf(mx, S[base + j] * scale);
    red[t] = mx; __syncthreads();
    for (int o = 128; o; o >>= 1) { if (t < o) red[t] = fmaxf(red[t], red[t + o]); __syncthreads(); }
    mx = red[0]; __syncthreads();
    float s = 0.f;
    for (int j = t; j < cols; j += 256) { float e = expf(S[base + j] * scale - mx); S[base + j] = e; s += e; }
    red[t] = s; __syncthreads();
    for (int o = 128; o; o >>= 1) { if (t < o) red[t] += red[t + o]; __syncthreads(); }
    float inv = 1.f / red[0];
    for (int j = t; j < cols; j += 256) S[base + j] *= inv;
}

// --------------------------------- head pieces ------------------------------
__global__ void gmaxmean_kernel(const float* __restrict__ xh, const float* __restrict__ mu,
                                const float* __restrict__ istd, float* __restrict__ g)
{
    int b = blockIdx.x;
    int o = blockIdx.y * 256 + threadIdx.x;
    float m = mu[o], is = istd[o];
    float mx = -FLT_MAX, s = 0.f;
    for (int n = 0; n < NPTS; n++) {
        float v = (xh[((size_t)(b * NPTS + n)) * 1024 + o] - m) * is;
        v = v >= 0.f ? v : NEGS * v;
        mx = fmaxf(mx, v); s += v;
    }
    g[b * 2112 + o] = mx;
    g[b * 2112 + 1024 + o] = s / (float)NPTS;
}

__global__ void cidcopy_kernel(const float* __restrict__ cid, float* __restrict__ g)
{
    int b = blockIdx.x, t = threadIdx.x;
    g[b * 2112 + 2048 + t] = cid[b * 64 + t];
}

__global__ void gvec_kernel(const float* __restrict__ Wc2, const float* __restrict__ g,
                            float* __restrict__ gv)
{
    int b = blockIdx.y;
    int j = blockIdx.x * 128 + threadIdx.x;
    const float* w = Wc2 + (size_t)j * 2240;
    const float* gb = g + b * 2112;
    float s = 0.f;
    for (int t = 0; t < 2112; t++) s += w[t] * gb[t];
    gv[b * 1024 + j] = s;
}

// ----------------------------------- host -----------------------------------
static void gemm(const float* A, const float* B, float* C, const float* R,
                 int M, int N, int K, int lda, int ldb, int ldc, int ldr,
                 long sA, long sB, long sC, long sR, int transB, int nz, int rmode)
{
    dim3 g((N + 63) / 64, (M + 63) / 64, nz);
    gemm_kernel<<<g, 256>>>(A, B, C, R, M, N, K, lda, ldb, ldc, ldr, sA, sB, sC, sR, transB, rmode);
}

static void bnstats(const float* X, int ldx, long rows, int C, float cntInv,
                    float* ps, float* pq, float* mu, float* is)
{
    int nblk = (int)((rows + 63) / 64);
    colstats_kernel<<<nblk, 256>>>(X, ldx, rows, C, ps, pq);
    reduce_stats_kernel<<<C, 256>>>(ps, pq, nblk, C, cntInv, mu, is);
}

static void bnleaky(const float* X, int ldx, float* Y, int ldy, const float* R, int ldr,
                    const float* mu, const float* is, long rows, int C)
{
    long tot = rows * (long)C;
    bn_leaky_kernel<<<(unsigned)((tot + 255) / 256), 256>>>(X, ldx, Y, ldy, R, ldr, mu, is, rows, C);
}

struct Ptrs {
    float *S, *xp, *sq, *A, *Bm, *h, *q, *k, *v, *o, *y, *f1, *ff, *hf, *hd, *hd2, *hu, *xt,
          *xh, *xc, *x3, *ot, *ps, *pq, *mu, *is, *wd, *rm, *ri, *sc, *g, *gc, *cid;
    int *idx, *sel;
};

static void n2p(Ptrs& P, const float* X, int ldx, int cin, int Np,
                const float* Wq, const float* Wk, const float* Wv, const float* Wo,
                const float* Wf1, const float* Wf2, float* out)
{
    long rows = (long)BATCH * Np;
    float cntInv = 1.f / (float)rows;
    // knn on X
    rowsumsq_kernel<<<(unsigned)((rows + 255) / 256), 256>>>(X, ldx, cin, rows, P.sq);
    gemm(X, X, P.S, 0, Np, Np, cin, ldx, ldx, Np, 0,
         (long)Np * ldx, (long)Np * ldx, (long)Np * Np, 0, 1, BATCH, 0);
    knn_select_kernel<<<dim3(Np, BATCH), 128>>>(P.S, P.sq, Np, P.idx);
    // q,k,v
    gemm(X, Wq, P.q, 0, (int)rows, 128, cin, ldx, cin, 128, 0, 0, 0, 0, 0, 1, 1, 0);
    gemm(X, Wk, P.k, 0, (int)rows, 128, cin, ldx, cin, 128, 0, 0, 0, 0, 0, 1, 1, 0);
    gemm(X, Wv, P.v, 0, (int)rows, 128, cin, ldx, cin, 128, 0, 0, 0, 0, 0, 1, 1, 0);
    attn_kernel<<<dim3(Np, BATCH), 128>>>(P.q, P.k, P.v, P.idx, P.o, Np);
    // y = leaky(bn(Wo@out))
    gemm(P.o, Wo, P.ff, 0, (int)rows, 128, 128, 128, 128, 128, 0, 0, 0, 0, 0, 1, 1, 0);
    bnstats(P.ff, 128, rows, 128, cntInv, P.ps, P.pq, P.mu, P.is);
    bnleaky(P.ff, 128, P.y, 128, 0, 0, P.mu, P.is, rows, 128);
    // f1 = leaky(bn(Wf1@y))
    gemm(P.y, Wf1, P.f1, 0, (int)rows, 512, 128, 128, 128, 512, 0, 0, 0, 0, 0, 1, 1, 0);
    bnstats(P.f1, 512, rows, 512, cntInv, P.ps, P.pq, P.mu, P.is);
    bnleaky(P.f1, 512, P.f1, 512, 0, 0, P.mu, P.is, rows, 512);
    // out = y + leaky(bn(Wf2@f1))
    gemm(P.f1, Wf2, P.ff, 0, (int)rows, 128, 512, 512, 512, 128, 0, 0, 0, 0, 0, 1, 1, 0);
    bnstats(P.ff, 128, rows, 128, cntInv, P.ps, P.pq, P.mu, P.is);
    bnleaky(P.ff, 128, out, 128, P.y, 128, P.mu, P.is, rows, 128);
}

extern "C" void kernel_launch(void* const* d_in, const int* in_sizes, int n_in,
                              void* d_out, int out_size)
{
    Ptrs P;
    cudaGetSymbolAddress((void**)&P.S, d_S);   cudaGetSymbolAddress((void**)&P.xp, d_xp);
    cudaGetSymbolAddress((void**)&P.sq, d_sq); cudaGetSymbolAddress((void**)&P.idx, d_idx);
    cudaGetSymbolAddress((void**)&P.A, d_A);   cudaGetSymbolAddress((void**)&P.Bm, d_Bm);
    cudaGetSymbolAddress((void**)&P.h, d_h);   cudaGetSymbolAddress((void**)&P.q, d_q);
    cudaGetSymbolAddress((void**)&P.k, d_k);   cudaGetSymbolAddress((void**)&P.v, d_v);
    cudaGetSymbolAddress((void**)&P.o, d_o);   cudaGetSymbolAddress((void**)&P.y, d_y);
    cudaGetSymbolAddress((void**)&P.f1, d_f1); cudaGetSymbolAddress((void**)&P.ff, d_ff);
    cudaGetSymbolAddress((void**)&P.hf, d_hf); cudaGetSymbolAddress((void**)&P.hd, d_hd);
    cudaGetSymbolAddress((void**)&P.hd2, d_hd2); cudaGetSymbolAddress((void**)&P.hu, d_hu);
    cudaGetSymbolAddress((void**)&P.xt, d_xt); cudaGetSymbolAddress((void**)&P.xh, d_xh);
    cudaGetSymbolAddress((void**)&P.xc, d_xc); cudaGetSymbolAddress((void**)&P.x3, d_x3);
    cudaGetSymbolAddress((void**)&P.ot, d_ot); cudaGetSymbolAddress((void**)&P.ps, d_ps);
    cudaGetSymbolAddress((void**)&P.pq, d_pq); cudaGetSymbolAddress((void**)&P.mu, d_mu);
    cudaGetSymbolAddress((void**)&P.is, d_is); cudaGetSymbolAddress((void**)&P.wd, d_wd);
    cudaGetSymbolAddress((void**)&P.rm, d_rm); cudaGetSymbolAddress((void**)&P.ri, d_ri);
    cudaGetSymbolAddress((void**)&P.sc, d_sc); cudaGetSymbolAddress((void**)&P.sel, d_sel);
    cudaGetSymbolAddress((void**)&P.g, d_g);   cudaGetSymbolAddress((void**)&P.gc, d_gc);
    cudaGetSymbolAddress((void**)&P.cid, d_cid);

    const float* x    = (const float*)d_in[0];
    const float* cat  = (const float*)d_in[1];
    const float* We0  = (const float*)d_in[2];
    const float* We1  = (const float*)d_in[3];
    const float* Wq0  = (const float*)d_in[4];
    const float* Wk0  = (const float*)d_in[5];
    const float* Wv0  = (const float*)d_in[6];
    const float* Wo0  = (const float*)d_in[7];
    const float* Wf10 = (const float*)d_in[8];
    const float* Wf20 = (const float*)d_in[9];
    const float* Wq1  = (const float*)d_in[10];
    const float* Wk1  = (const float*)d_in[11];
    const float* Wv1  = (const float*)d_in[12];
    const float* Wo1  = (const float*)d_in[13];
    const float* Wf11 = (const float*)d_in[14];
    const float* Wf21 = (const float*)d_in[15];
    const float* Wq2  = (const float*)d_in[16];
    const float* Wk2  = (const float*)d_in[17];
    const float* Wv2  = (const float*)d_in[18];
    const float* Wo2  = (const float*)d_in[19];
    const float* Wf12 = (const float*)d_in[20];
    const float* Wf22 = (const float*)d_in[21];
    const float* Wdq  = (const float*)d_in[22];
    const float* Wdk  = (const float*)d_in[23];
    const float* Wuq  = (const float*)d_in[24];
    const float* Wuk  = (const float*)d_in[25];
    const float* Wuv  = (const float*)d_in[26];
    const float* Wc   = (const float*)d_in[27];
    const float* Wc1  = (const float*)d_in[28];
    const float* Wc2  = (const float*)d_in[29];
    const float* Wc3  = (const float*)d_in[30];
    const float* Wc4  = (const float*)d_in[31];
    float* out = (float*)d_out;

    const long R16 = (long)BATCH * NPTS;     // 16384
    const long R8  = (long)BATCH * MPTS;     // 8192

    // -------- input transpose --------
    tin_kernel<<<(BATCH * NPTS * 3 + 255) / 256, 256>>>(x, P.xp);

    // -------- edge conv 1 (3ch -> 128) --------
    wdiff_kernel<<<(128 * 3 + 255) / 256, 256>>>(We0, P.wd, 128, 3, 6);
    gemm(P.xp, P.wd, P.A, 0, (int)R16, 128, 3, 3, 3, 128, 0, 0, 0, 0, 0, 1, 1, 0);
    gemm(P.xp, We0 + 3, P.Bm, 0, (int)R16, 128, 3, 3, 6, 128, 0, 0, 0, 0, 0, 1, 1, 0);
    rowsumsq_kernel<<<(unsigned)((R16 + 255) / 256), 256>>>(P.xp, 3, 3, R16, P.sq);
    gemm(P.xp, P.xp, P.S, 0, NPTS, NPTS, 3, 3, 3, NPTS,
         0, (long)NPTS * 3, (long)NPTS * 3, (long)NPTS * NPTS, 0, 1, BATCH, 0);
    knn_select_kernel<<<dim3(NPTS, BATCH), 128>>>(P.S, P.sq, NPTS, P.idx);
    edge_gather_kernel<<<dim3(NPTS, BATCH), 128>>>(P.A, P.Bm, P.idx, P.h, 256, P.ps, P.pq, NPTS);
    reduce_stats_kernel<<<128, 256>>>(P.ps, P.pq, (int)R16, 128, 1.f / (float)(R16 * KNN), P.mu, P.is);
    bnleaky(P.h, 256, P.h, 256, 0, 0, P.mu, P.is, R16, 128);

    // -------- edge conv 2 (e0:128 -> 128, written to h[:,128:256]) --------
    wdiff_kernel<<<(128 * 128 + 255) / 256, 256>>>(We1, P.wd, 128, 128, 256);
    gemm(P.h, P.wd, P.A, 0, (int)R16, 128, 128, 256, 128, 128, 0, 0, 0, 0, 0, 1, 1, 0);
    gemm(P.h, We1 + 128, P.Bm, 0, (int)R16, 128, 128, 256, 256, 128, 0, 0, 0, 0, 0, 1, 1, 0);
    rowsumsq_kernel<<<(unsigned)((R16 + 255) / 256), 256>>>(P.h, 256, 128, R16, P.sq);
    gemm(P.h, P.h, P.S, 0, NPTS, NPTS, 128, 256, 256, NPTS,
         0, (long)NPTS * 256, (long)NPTS * 256, (long)NPTS * NPTS, 0, 1, BATCH, 0);
    knn_select_kernel<<<dim3(NPTS, BATCH), 128>>>(P.S, P.sq, NPTS, P.idx);
    edge_gather_kernel<<<dim3(NPTS, BATCH), 128>>>(P.A, P.Bm, P.idx, P.h + 128, 256, P.ps, P.pq, NPTS);
    reduce_stats_kernel<<<128, 256>>>(P.ps, P.pq, (int)R16, 128, 1.f / (float)(R16 * KNN), P.mu, P.is);
    bnleaky(P.h + 128, 256, P.h + 128, 256, 0, 0, P.mu, P.is, R16, 128);

    // -------- n2p layer 0 on h (256ch) -> h_full --------
    n2p(P, P.h, 256, 256, NPTS, Wq0, Wk0, Wv0, Wo0, Wf10, Wf20, P.hf);

    // -------- down_global --------
    gemm(P.hf, Wdq, P.q, 0, (int)R16, 128, 128, 128, 128, 128, 0, 0, 0, 0, 0, 1, 1, 0);
    gemm(P.hf, Wdk, P.k, 0, (int)R16, 128, 128, 128, 128, 128, 0, 0, 0, 0, 0, 1, 1, 0);
    gemm(P.q, P.k, P.S, 0, NPTS, NPTS, 128, 128, 128, NPTS,
         0, (long)NPTS * 128, (long)NPTS * 128, (long)NPTS * NPTS, 0, 1, BATCH, 0);
    rowstats_kernel<<<dim3(NPTS, BATCH), 256>>>(P.S, NPTS, P.rm, P.ri);
    colscore_kernel<<<dim3(NPTS / 128, BATCH), 128>>>(P.S, NPTS, P.rm, P.ri, P.sc);
    topm_kernel<<<BATCH, 1024>>>(P.sc, P.sel);
    gather_rows_kernel<<<dim3(MPTS, BATCH), 128>>>(P.hf, P.sel, P.hd);

    // -------- n2p layer 1 on hd (1024 pts) --------
    n2p(P, P.hd, 128, 128, MPTS, Wq1, Wk1, Wv1, Wo1, Wf11, Wf21, P.hd2);

    // -------- up_cross(hf, hd2) --------
    gemm(P.hf, Wuq, P.q, 0, (int)R16, 128, 128, 128, 128, 128, 0, 0, 0, 0, 0, 1, 1, 0);
    gemm(P.hd2, Wuk, P.k, 0, (int)R8, 128, 128, 128, 128, 128, 0, 0, 0, 0, 0, 1, 1, 0);
    gemm(P.hd2, Wuv, P.v, 0, (int)R8, 128, 128, 128, 128, 128, 0, 0, 0, 0, 0, 1, 1, 0);
    gemm(P.q, P.k, P.S, 0, NPTS, MPTS, 128, 128, 128, MPTS,
         0, (long)NPTS * 128, (long)MPTS * 128, (long)NPTS * MPTS, 0, 1, BATCH, 0);
    row_softmax_kernel<<<(unsigned)R16, 256>>>(P.S, MPTS, ASCALE);
    gemm(P.S, P.v, P.hu, P.hf, NPTS, 128, MPTS, MPTS, 128, 128, 128,
         (long)NPTS * MPTS, (long)MPTS * 128, (long)NPTS * 128, (long)NPTS * 128, 0, BATCH, 1);

    // -------- n2p layer 2 on hu -> x_tmp --------
    n2p(P, P.hu, 128, 128, NPTS, Wq2, Wk2, Wv2, Wo2, Wf12, Wf22, P.xt);

    // -------- head --------
    // cid = leaky(bn(Wc1@category_id))
    gemm(cat, Wc1, P.cid, 0, BATCH, 64, 16, 16, 16, 64, 0, 0, 0, 0, 0, 1, 1, 0);
    bnstats(P.cid, 64, BATCH, 64, 1.f / (float)BATCH, P.ps, P.pq, P.mu, P.is);
    bnleaky(P.cid, 64, P.cid, 64, 0, 0, P.mu, P.is, BATCH, 64);
    // xh = Wc@x_tmp (pre-bn); fused bn+leaky inside max/mean reduction
    gemm(P.xt, Wc, P.xh, 0, (int)R16, 1024, 128, 128, 128, 1024, 0, 0, 0, 0, 0, 1, 1, 0);
    bnstats(P.xh, 1024, R16, 1024, 1.f / (float)R16, P.ps, P.pq, P.mu, P.is);
    gmaxmean_kernel<<<dim3(BATCH, 4), 256>>>(P.xh, P.mu, P.is, P.g);
    cidcopy_kernel<<<BATCH, 64>>>(P.cid, P.g);
    // gvec[b] = Wc2[:, :2112] @ g[b]
    gvec_kernel<<<dim3(8, BATCH), 128>>>(Wc2, P.g, P.gc);
    // xc = leaky(bn(gvec + Wc2[:,2112:]@x_tmp))
    gemm(P.xt, Wc2 + 2112, P.xc, P.gc, (int)R16, 1024, 128, 128, 2240, 1024, 1024,
         0, 0, 0, 0, 1, 1, 2);
    bnstats(P.xc, 1024, R16, 1024, 1.f / (float)R16, P.ps, P.pq, P.mu, P.is);
    bnleaky(P.xc, 1024, P.xc, 1024, 0, 0, P.mu, P.is, R16, 1024);
    // xc3 = leaky(bn(Wc3@xc))
    gemm(P.xc, Wc3, P.x3, 0, (int)R16, 256, 1024, 1024, 1024, 256, 0, 0, 0, 0, 0, 1, 1, 0);
    bnstats(P.x3, 256, R16, 256, 1.f / (float)R16, P.ps, P.pq, P.mu, P.is);
    bnleaky(P.x3, 256, P.x3, 256, 0, 0, P.mu, P.is, R16, 256);
    // out = Wc4@xc3
    gemm(P.x3, Wc4, P.ot, 0, (int)R16, 50, 256, 256, 256, 50, 0, 0, 0, 0, 0, 1, 1, 0);
    tout_kernel<<<(BATCH * 50 * NPTS + 255) / 256, 256>>>(P.ot, out);
}

// round 13
// speedup vs baseline: 1.3441x; 1.3441x over previous
#include <cuda_runtime.h>
#include <math.h>
#include <float.h>

#define BATCH 8
#define NPTS  2048
#define MPTS  1024
#define KNN   32
#define NEGS  0.2f
#define ASCALE 0.08838834764831845f  /* 1/sqrt(128) */

// ------------------------------ device scratch ------------------------------
__device__ float d_S[(size_t)BATCH*NPTS*NPTS];          // Grams / attention S
__device__ float d_xp[BATCH*NPTS*3];
__device__ float d_sq[BATCH*NPTS];
__device__ int   d_idx[BATCH*NPTS*KNN];
__device__ float d_A [BATCH*NPTS*128];
__device__ float d_Bm[BATCH*NPTS*128];
__device__ float d_h [BATCH*NPTS*256];                  // [e0 | e1]
__device__ float d_q [BATCH*NPTS*128];
__device__ float d_k [BATCH*NPTS*128];
__device__ float d_v [BATCH*NPTS*128];
__device__ float d_o [BATCH*NPTS*128];
__device__ float d_y [BATCH*NPTS*128];
__device__ float d_f1[(size_t)BATCH*NPTS*512];
__device__ float d_ff[BATCH*NPTS*128];
__device__ float d_hf[BATCH*NPTS*128];                  // h_full
__device__ float d_hd [BATCH*MPTS*128];
__device__ float d_hd2[BATCH*MPTS*128];
__device__ float d_hu[BATCH*NPTS*128];
__device__ float d_xt[BATCH*NPTS*128];                  // x_tmp
__device__ float d_xh[(size_t)BATCH*NPTS*1024];
__device__ float d_xc[(size_t)BATCH*NPTS*1024];
__device__ float d_x3[BATCH*NPTS*256];
__device__ float d_ot[BATCH*NPTS*50];
__device__ float d_ps[(size_t)BATCH*NPTS*128];          // stat partial sums
__device__ float d_pq[(size_t)BATCH*NPTS*128];          // stat partial sumsq
__device__ float d_mu[1024];
__device__ float d_is[1024];
__device__ float d_wd[128*128];
__device__ float d_rm[BATCH*NPTS];
__device__ float d_ri[BATCH*NPTS];
__device__ float d_sc[BATCH*NPTS];
__device__ int   d_sel[BATCH*MPTS];
__device__ float d_g [BATCH*2112];
__device__ float d_gc[BATCH*1024];
__device__ float d_cid[BATCH*64];

// ------------------------------ GEMM (fp32 tiled, generic/small) ------------
// C[i,j] = sum_k A[i,k] * (transB ? B[j,k] : B[k,j]); rmode: 0 none,
// 1: += R[i*ldr+j] (with z-stride sR), 2: += R[(i>>11)*ldr+j] (per-batch row vec)
#define GBK 16
__global__ void gemm_kernel(const float* __restrict__ A, const float* __restrict__ B,
                            float* __restrict__ C, const float* __restrict__ R,
                            int M, int N, int Kd, int lda, int ldb, int ldc, int ldr,
                            long sA, long sB, long sC, long sR, int transB, int rmode)
{
    __shared__ float As[GBK][64];
    __shared__ float Bs[GBK][64];
    int bz = blockIdx.z;
    A += (size_t)bz * sA; B += (size_t)bz * sB; C += (size_t)bz * sC;
    if (R && rmode == 1) R += (size_t)bz * sR;
    int bm = blockIdx.y * 64, bn = blockIdx.x * 64;
    int tid = threadIdx.x;
    int tm = (tid >> 4) << 2;
    int tn = (tid & 15) << 2;
    float acc[4][4];
#pragma unroll
    for (int i = 0; i < 4; i++)
#pragma unroll
        for (int j = 0; j < 4; j++) acc[i][j] = 0.f;

    for (int k0 = 0; k0 < Kd; k0 += GBK) {
#pragma unroll
        for (int i = 0; i < 4; i++) {
            int idx = tid + i * 256;
            int m = idx >> 4, kk = idx & 15;
            int gm = bm + m, gk = k0 + kk;
            As[kk][m] = (gm < M && gk < Kd) ? A[(size_t)gm * lda + gk] : 0.f;
        }
        if (transB) {
#pragma unroll
            for (int i = 0; i < 4; i++) {
                int idx = tid + i * 256;
                int n = idx >> 4, kk = idx & 15;
                int gn = bn + n, gk = k0 + kk;
                Bs[kk][n] = (gn < N && gk < Kd) ? B[(size_t)gn * ldb + gk] : 0.f;
            }
        } else {
#pragma unroll
            for (int i = 0; i < 4; i++) {
                int idx = tid + i * 256;
                int kk = idx >> 6, n = idx & 63;
                int gn = bn + n, gk = k0 + kk;
                Bs[kk][n] = (gn < N && gk < Kd) ? B[(size_t)gk * ldb + gn] : 0.f;
            }
        }
        __syncthreads();
#pragma unroll
        for (int kk = 0; kk < GBK; kk++) {
            float a0 = As[kk][tm], a1 = As[kk][tm+1], a2 = As[kk][tm+2], a3 = As[kk][tm+3];
            float b0 = Bs[kk][tn], b1 = Bs[kk][tn+1], b2 = Bs[kk][tn+2], b3 = Bs[kk][tn+3];
            acc[0][0]+=a0*b0; acc[0][1]+=a0*b1; acc[0][2]+=a0*b2; acc[0][3]+=a0*b3;
            acc[1][0]+=a1*b0; acc[1][1]+=a1*b1; acc[1][2]+=a1*b2; acc[1][3]+=a1*b3;
            acc[2][0]+=a2*b0; acc[2][1]+=a2*b1; acc[2][2]+=a2*b2; acc[2][3]+=a2*b3;
            acc[3][0]+=a3*b0; acc[3][1]+=a3*b1; acc[3][2]+=a3*b2; acc[3][3]+=a3*b3;
        }
        __syncthreads();
    }
#pragma unroll
    for (int i = 0; i < 4; i++) {
        int gm = bm + tm + i;
        if (gm >= M) continue;
#pragma unroll
        for (int j = 0; j < 4; j++) {
            int gn = bn + tn + j;
            if (gn >= N) continue;
            float vv = acc[i][j];
            if (rmode == 1) vv += R[(size_t)gm * ldr + gn];
            else if (rmode == 2) vv += R[(size_t)(gm >> 11) * ldr + gn];
            C[(size_t)gm * ldc + gn] = vv;
        }
    }
}

// ------------------- GEMM fast path: 128x128x16, 8x8/thread -----------------
// Requirements (checked by dispatcher): K%16==0, lda%4==0, ldb%4==0,
// and (transB || N%4==0). Same k-accumulation order as gemm_kernel
// (k0 ascending, kk ascending) -> bit-identical results.
#define FBM 128
#define FBN 128
#define FBK 16
__global__ __launch_bounds__(256, 2)
void gemm_fast_kernel(const float* __restrict__ A, const float* __restrict__ B,
                      float* __restrict__ C, const float* __restrict__ R,
                      int M, int N, int Kd, int lda, int ldb, int ldc, int ldr,
                      long sA, long sB, long sC, long sR, int transB, int rmode)
{
    __shared__ float As[FBK][FBM + 4];
    __shared__ float Bs[FBK][FBN + 4];
    int bz = blockIdx.z;
    A += (size_t)bz * sA; B += (size_t)bz * sB; C += (size_t)bz * sC;
    if (R && rmode == 1) R += (size_t)bz * sR;
    int bm = blockIdx.y * FBM, bn = blockIdx.x * FBN;
    int tid = threadIdx.x;
    int tm = (tid >> 4) << 3;        // 0..120 step 8
    int tn = (tid & 15) << 3;        // 0..120 step 8

    float acc[8][8];
#pragma unroll
    for (int i = 0; i < 8; i++)
#pragma unroll
        for (int j = 0; j < 8; j++) acc[i][j] = 0.f;

    for (int k0 = 0; k0 < Kd; k0 += FBK) {
        // ---- load A tile: 128 rows x 16 k = 512 float4, 2 per thread ----
#pragma unroll
        for (int i = 0; i < 2; i++) {
            int idx = tid + i * 256;            // 0..511
            int m  = idx >> 2;                  // 0..127
            int kq = (idx & 3) << 2;            // 0,4,8,12
            int gm = bm + m;
            float4 v = make_float4(0.f, 0.f, 0.f, 0.f);
            if (gm < M) v = *(const float4*)(A + (size_t)gm * lda + (k0 + kq));
            As[kq + 0][m] = v.x; As[kq + 1][m] = v.y;
            As[kq + 2][m] = v.z; As[kq + 3][m] = v.w;
        }
        // ---- load B tile ----
        if (transB) {
#pragma unroll
            for (int i = 0; i < 2; i++) {
                int idx = tid + i * 256;
                int n  = idx >> 2;
                int kq = (idx & 3) << 2;
                int gn = bn + n;
                float4 v = make_float4(0.f, 0.f, 0.f, 0.f);
                if (gn < N) v = *(const float4*)(B + (size_t)gn * ldb + (k0 + kq));
                Bs[kq + 0][n] = v.x; Bs[kq + 1][n] = v.y;
                Bs[kq + 2][n] = v.z; Bs[kq + 3][n] = v.w;
            }
        } else {
#pragma unroll
            for (int i = 0; i < 2; i++) {
                int idx = tid + i * 256;
                int kk = idx >> 5;                  // 0..15
                int n4 = (idx & 31) << 2;           // 0..124
                int gn = bn + n4;
                float4 v = make_float4(0.f, 0.f, 0.f, 0.f);
                if (gn < N) v = *(const float4*)(B + (size_t)(k0 + kk) * ldb + gn);
                *(float4*)&Bs[kk][n4] = v;
            }
        }
        __syncthreads();
#pragma unroll
        for (int kk = 0; kk < FBK; kk++) {
            float4 a0 = *(const float4*)&As[kk][tm];
            float4 a1 = *(const float4*)&As[kk][tm + 4];
            float4 b0 = *(const float4*)&Bs[kk][tn];
            float4 b1 = *(const float4*)&Bs[kk][tn + 4];
            float ar[8] = {a0.x, a0.y, a0.z, a0.w, a1.x, a1.y, a1.z, a1.w};
            float br[8] = {b0.x, b0.y, b0.z, b0.w, b1.x, b1.y, b1.z, b1.w};
#pragma unroll
            for (int i = 0; i < 8; i++)
#pragma unroll
                for (int j = 0; j < 8; j++) acc[i][j] += ar[i] * br[j];
        }
        __syncthreads();
    }
    // ---- epilogue ----
#pragma unroll
    for (int i = 0; i < 8; i++) {
        int gm = bm + tm + i;
        if (gm >= M) continue;
#pragma unroll
        for (int j = 0; j < 8; j++) {
            int gn = bn + tn + j;
            if (gn >= N) continue;
            float vv = acc[i][j];
            if (rmode == 1) vv += R[(size_t)gm * ldr + gn];
            else if (rmode == 2) vv += R[(size_t)(gm >> 11) * ldr + gn];
            C[(size_t)gm * ldc + gn] = vv;
        }
    }
}

// --------------------------- misc small kernels -----------------------------
__global__ void tin_kernel(const float* __restrict__ x, float* __restrict__ xp)
{
    int e = blockIdx.x * blockDim.x + threadIdx.x;
    if (e >= BATCH * NPTS * 3) return;
    int b = e / (NPTS * 3), r = e % (NPTS * 3);
    int n = r / 3, c = r % 3;
    xp[e] = x[(size_t)b * 3 * NPTS + (size_t)c * NPTS + n];
}

__global__ void tout_kernel(const float* __restrict__ t, float* __restrict__ out)
{
    int e = blockIdx.x * blockDim.x + threadIdx.x;
    if (e >= BATCH * 50 * NPTS) return;
    int b = e / (50 * NPTS), r = e % (50 * NPTS);
    int o = r / NPTS, n = r % NPTS;
    out[e] = t[((size_t)b * NPTS + n) * 50 + o];
}

__global__ void wdiff_kernel(const float* __restrict__ W, float* __restrict__ wd,
                             int Cout, int Cin, int ldw)
{
    int e = blockIdx.x * blockDim.x + threadIdx.x;
    if (e >= Cout * Cin) return;
    int o = e / Cin, c = e % Cin;
    wd[e] = W[o * ldw + c] - W[o * ldw + Cin + c];
}

__global__ void rowsumsq_kernel(const float* __restrict__ X, int ldx, int C,
                                long rows, float* __restrict__ sq)
{
    long r = (long)blockIdx.x * blockDim.x + threadIdx.x;
    if (r >= rows) return;
    const float* p = X + (size_t)r * ldx;
    float s = 0.f;
    for (int c = 0; c < C; c++) s += p[c] * p[c];
    sq[r] = s;
}

// --------------------------------- knn select -------------------------------
__global__ void knn_select_kernel(const float* __restrict__ inner, const float* __restrict__ sq,
                                  int Np, int* __restrict__ idxOut)
{
    __shared__ float sval[2048];
    __shared__ float cmin[128];
    __shared__ int   cidx[128];
    __shared__ int   ssel;
    int b = blockIdx.y, n = blockIdx.x, t = threadIdx.x;
    const float* row = inner + ((size_t)b * Np + n) * (size_t)Np;
    const float* sqb = sq + (size_t)b * Np;
    float sqn = sqb[n];
    for (int m = t; m < Np; m += 128) sval[m] = sqn - 2.f * row[m] + sqb[m];
    __syncthreads();
    int chunk = Np >> 7;
    int base = t * chunk;
    float lmin = FLT_MAX; int lidx = base;
    for (int i = 0; i < chunk; i++) { float v = sval[base + i]; if (v < lmin) { lmin = v; lidx = base + i; } }
    int* orow = idxOut + ((size_t)b * Np + n) * KNN;
    for (int s = 0; s < KNN; s++) {
        cmin[t] = lmin; cidx[t] = lidx;
        __syncthreads();
        for (int off = 64; off > 0; off >>= 1) {
            if (t < off) {
                float v2 = cmin[t + off]; int i2 = cidx[t + off];
                if (v2 < cmin[t] || (v2 == cmin[t] && i2 < cidx[t])) { cmin[t] = v2; cidx[t] = i2; }
            }
            __syncthreads();
        }
        if (t == 0) { orow[s] = cidx[0]; ssel = cidx[0]; }
        __syncthreads();
        int sel = ssel;
        if (sel >= base && sel < base + chunk) {
            sval[sel] = FLT_MAX;
            lmin = FLT_MAX; lidx = base;
            for (int i = 0; i < chunk; i++) { float v = sval[base + i]; if (v < lmin) { lmin = v; lidx = base + i; } }
        }
        __syncthreads();
    }
}

// -------------------------- edge-conv gather+max+stats ----------------------
__global__ void edge_gather_kernel(const float* __restrict__ At, const float* __restrict__ Bt,
                                   const int* __restrict__ idx, float* __restrict__ out, int ldo,
                                   float* __restrict__ ps, float* __restrict__ pq, int Np)
{
    __shared__ int sidx[KNN];
    int b = blockIdx.y, n = blockIdx.x, t = threadIdx.x;
    size_t pbase = (size_t)b * Np + n;
    if (t < KNN) sidx[t] = idx[pbase * KNN + t];
    __syncthreads();
    float a = At[pbase * 128 + t];
    float s = 0.f, q = 0.f, mx = -FLT_MAX;
#pragma unroll
    for (int k = 0; k < KNN; k++) {
        float v = a + Bt[((size_t)b * Np + sidx[k]) * 128 + t];
        s += v; q += v * v; mx = fmaxf(mx, v);
    }
    out[pbase * ldo + t] = mx;
    ps[pbase * 128 + t] = s;
    pq[pbase * 128 + t] = q;
}

// ------------------------------ batch-norm pieces ---------------------------
__global__ void colstats_kernel(const float* __restrict__ X, int ldx, long rows, int C,
                                float* __restrict__ ps, float* __restrict__ pq)
{
    int blk = blockIdx.x, t = threadIdx.x;
    long r0 = (long)blk * 64;
    long r1 = r0 + 64; if (r1 > rows) r1 = rows;
    for (int c = t; c < C; c += 256) {
        float s = 0.f, q = 0.f;
        for (long r = r0; r < r1; r++) { float v = X[(size_t)r * ldx + c]; s += v; q += v * v; }
        ps[(size_t)blk * C + c] = s;
        pq[(size_t)blk * C + c] = q;
    }
}

__global__ void reduce_stats_kernel(const float* __restrict__ ps, const float* __restrict__ pq,
                                    int nblk, int C, float cntInv,
                                    float* __restrict__ mu, float* __restrict__ istd)
{
    __shared__ float rs[256], rq[256];
    int c = blockIdx.x, t = threadIdx.x;
    float s = 0.f, q = 0.f;
    for (int i = t; i < nblk; i += 256) { s += ps[(size_t)i * C + c]; q += pq[(size_t)i * C + c]; }
    rs[t] = s; rq[t] = q;
    __syncthreads();
    for (int off = 128; off > 0; off >>= 1) {
        if (t < off) { rs[t] += rs[t + off]; rq[t] += rq[t + off]; }
        __syncthreads();
    }
    if (t == 0) {
        float m = rs[0] * cntInv;
        float var = rq[0] * cntInv - m * m;
        mu[c] = m;
        istd[c] = rsqrtf(var + 1e-5f);
    }
}

__global__ void bn_leaky_kernel(const float* __restrict__ X, int ldx, float* __restrict__ Y, int ldy,
                                const float* __restrict__ R, int ldr,
                                const float* __restrict__ mu, const float* __restrict__ istd,
                                long rows, int C)
{
    long e = (long)blockIdx.x * blockDim.x + threadIdx.x;
    if (e >= rows * (long)C) return;
    long r = e / C; int c = (int)(e % C);
    float v = (X[(size_t)r * ldx + c] - mu[c]) * istd[c];
    v = v >= 0.f ? v : NEGS * v;
    if (R) v += R[(size_t)r * ldr + c];
    Y[(size_t)r * ldy + c] = v;
}

// ------------------------------ local knn attention -------------------------
__global__ void attn_kernel(const float* __restrict__ Q, const float* __restrict__ Kf,
                            const float* __restrict__ Vf, const int* __restrict__ idx,
                            float* __restrict__ O, int Np)
{
    __shared__ float qs[128];
    __shared__ float Ks[32 * 129];
    __shared__ int   sidx[KNN];
    __shared__ float sa[KNN];
    int b = blockIdx.y, n = blockIdx.x, t = threadIdx.x;
    size_t pbase = (size_t)b * Np + n;
    qs[t] = Q[pbase * 128 + t];
    if (t < KNN) sidx[t] = idx[pbase * KNN + t];
    __syncthreads();
    for (int e = t; e < KNN * 128; e += 128) {
        int k = e >> 7, c = e & 127;
        Ks[k * 129 + c] = Kf[((size_t)b * Np + sidx[k]) * 128 + c];
    }
    __syncthreads();
    if (t < KNN) {
        float dv = 0.f;
        for (int c = 0; c < 128; c++) dv += qs[c] * Ks[t * 129 + c];
        dv *= ASCALE;
        float mx = dv;
        for (int off = 16; off; off >>= 1) mx = fmaxf(mx, __shfl_xor_sync(0xffffffffu, mx, off));
        float ee = expf(dv - mx);
        float sm = ee;
        for (int off = 16; off; off >>= 1) sm += __shfl_xor_sync(0xffffffffu, sm, off);
        sa[t] = ee / sm;
    }
    __syncthreads();
    float acc = 0.f;
#pragma unroll
    for (int k = 0; k < KNN; k++) acc += sa[k] * Vf[((size_t)b * Np + sidx[k]) * 128 + t];
    O[pbase * 128 + t] = acc;
}

// ------------------------------ down_global pieces --------------------------
__global__ void rowstats_kernel(const float* __restrict__ S, int Np,
                                float* __restrict__ rmax, float* __restrict__ rsinv)
{
    __shared__ float red[256];
    int b = blockIdx.y, n = blockIdx.x, t = threadIdx.x;
    const float* row = S + ((size_t)b * Np + n) * (size_t)Np;
    float mx = -FLT_MAX;
    for (int m = t; m < Np; m += 256) mx = fmaxf(mx, row[m] * ASCALE);
    red[t] = mx;
    __syncthreads();
    for (int off = 128; off > 0; off >>= 1) { if (t < off) red[t] = fmaxf(red[t], red[t + off]); __syncthreads(); }
    float g = red[0];
    __syncthreads();
    float s = 0.f;
    for (int m = t; m < Np; m += 256) s += expf(row[m] * ASCALE - g);
    red[t] = s;
    __syncthreads();
    for (int off = 128; off > 0; off >>= 1) { if (t < off) red[t] += red[t + off]; __syncthreads(); }
    if (t == 0) { rmax[b * Np + n] = g; rsinv[b * Np + n] = 1.f / red[0]; }
}

__global__ void colscore_kernel(const float* __restrict__ S, int Np,
                                const float* __restrict__ rmax, const float* __restrict__ rsinv,
                                float* __restrict__ score)
{
    int b = blockIdx.y;
    int m = blockIdx.x * 128 + threadIdx.x;
    const float* Sb = S + (size_t)b * Np * Np;
    const float* rm = rmax + b * Np;
    const float* ri = rsinv + b * Np;
    float acc = 0.f;
    for (int n = 0; n < Np; n++) acc += expf(Sb[(size_t)n * Np + m] * ASCALE - rm[n]) * ri[n];
    score[b * Np + m] = acc / (float)Np;
}

__global__ void topm_kernel(const float* __restrict__ score, int* __restrict__ sel)
{
    __shared__ float sv[2048];
    __shared__ int   si[2048];
    int b = blockIdx.x, t = threadIdx.x;
    for (int i = t; i < 2048; i += 1024) { sv[i] = score[b * 2048 + i]; si[i] = i; }
    __syncthreads();
    for (int k = 2; k <= 2048; k <<= 1) {
        for (int j = k >> 1; j > 0; j >>= 1) {
            for (int w = t; w < 2048; w += 1024) {
                int ixj = w ^ j;
                if (ixj > w) {
                    bool dir = ((w & k) == 0);
                    float va = sv[w], vb = sv[ixj];
                    int ia = si[w], ib = si[ixj];
                    bool bBetter = (vb > va) || (vb == va && ib < ia);
                    if (bBetter == dir) { sv[w] = vb; si[w] = ib; sv[ixj] = va; si[ixj] = ia; }
                }
            }
            __syncthreads();
        }
    }
    for (int i = t; i < 1024; i += 1024) sel[b * 1024 + i] = si[i];
}

__global__ void gather_rows_kernel(const float* __restrict__ X, const int* __restrict__ sel,
                                   float* __restrict__ Y)
{
    int b = blockIdx.y, j = blockIdx.x, t = threadIdx.x;
    Y[((size_t)b * MPTS + j) * 128 + t] = X[((size_t)b * NPTS + sel[b * MPTS + j]) * 128 + t];
}

// -------------------------------- up softmax --------------------------------
__global__ void row_softmax_kernel(float* __restrict__ S, int cols, float scale)
{
    __shared__ float red[256];
    size_t base = (size_t)blockIdx.x * cols;
    int t = threadIdx.x;
    float mx = -FLT_MAX;
    for (int j = t; j < cols; j += 256) mx = fmaxf(mx, S[base + j] * scale);
    red[t] = mx; __syncthreads();
    for (int o = 128; o; o >>= 1) { if (t < o) red[t] = fmaxf(red[t], red[t + o]); __syncthreads(); }
    mx = red[0]; __syncthreads();
    float s = 0.f;
    for (int j = t; j < cols; j += 256) { float e = expf(S[base + j] * scale - mx); S[base + j] = e; s += e; }
    red[t] = s; __syncthreads();
    for (int o = 128; o; o >>= 1) { if (t < o) red[t] += red[t + o]; __syncthreads(); }
    float inv = 1.f / red[0];
    for (int j = t; j < cols; j += 256) S[base + j] *= inv;
}

// --------------------------------- head pieces ------------------------------
__global__ void gmaxmean_kernel(const float* __restrict__ xh, const float* __restrict__ mu,
                                const float* __restrict__ istd, float* __restrict__ g)
{
    int b = blockIdx.x;
    int o = blockIdx.y * 256 + threadIdx.x;
    float m = mu[o], is = istd[o];
    float mx = -FLT_MAX, s = 0.f;
    for (int n = 0; n < NPTS; n++) {
        float v = (xh[((size_t)(b * NPTS + n)) * 1024 + o] - m) * is;
        v = v >= 0.f ? v : NEGS * v;
        mx = fmaxf(mx, v); s += v;
    }
    g[b * 2112 + o] = mx;
    g[b * 2112 + 1024 + o] = s / (float)NPTS;
}

__global__ void cidcopy_kernel(const float* __restrict__ cid, float* __restrict__ g)
{
    int b = blockIdx.x, t = threadIdx.x;
    g[b * 2112 + 2048 + t] = cid[b * 64 + t];
}

__global__ void gvec_kernel(const float* __restrict__ Wc2, const float* __restrict__ g,
                            float* __restrict__ gv)
{
    int b = blockIdx.y;
    int j = blockIdx.x * 128 + threadIdx.x;
    const float* w = Wc2 + (size_t)j * 2240;
    const float* gb = g + b * 2112;
    float s = 0.f;
    for (int t = 0; t < 2112; t++) s += w[t] * gb[t];
    gv[b * 1024 + j] = s;
}

// ----------------------------------- host -----------------------------------
static void gemm(const float* A, const float* B, float* C, const float* R,
                 int M, int N, int K, int lda, int ldb, int ldc, int ldr,
                 long sA, long sB, long sC, long sR, int transB, int nz, int rmode)
{
    bool fast = (K % 16 == 0) && (lda % 4 == 0) && (ldb % 4 == 0) &&
                (transB || (N % 4 == 0));
    if (fast) {
        dim3 g((N + FBN - 1) / FBN, (M + FBM - 1) / FBM, nz);
        gemm_fast_kernel<<<g, 256>>>(A, B, C, R, M, N, K, lda, ldb, ldc, ldr,
                                     sA, sB, sC, sR, transB, rmode);
    } else {
        dim3 g((N + 63) / 64, (M + 63) / 64, nz);
        gemm_kernel<<<g, 256>>>(A, B, C, R, M, N, K, lda, ldb, ldc, ldr,
                                sA, sB, sC, sR, transB, rmode);
    }
}

static void bnstats(const float* X, int ldx, long rows, int C, float cntInv,
                    float* ps, float* pq, float* mu, float* is)
{
    int nblk = (int)((rows + 63) / 64);
    colstats_kernel<<<nblk, 256>>>(X, ldx, rows, C, ps, pq);
    reduce_stats_kernel<<<C, 256>>>(ps, pq, nblk, C, cntInv, mu, is);
}

static void bnleaky(const float* X, int ldx, float* Y, int ldy, const float* R, int ldr,
                    const float* mu, const float* is, long rows, int C)
{
    long tot = rows * (long)C;
    bn_leaky_kernel<<<(unsigned)((tot + 255) / 256), 256>>>(X, ldx, Y, ldy, R, ldr, mu, is, rows, C);
}

struct Ptrs {
    float *S, *xp, *sq, *A, *Bm, *h, *q, *k, *v, *o, *y, *f1, *ff, *hf, *hd, *hd2, *hu, *xt,
          *xh, *xc, *x3, *ot, *ps, *pq, *mu, *is, *wd, *rm, *ri, *sc, *g, *gc, *cid;
    int *idx, *sel;
};

static void n2p(Ptrs& P, const float* X, int ldx, int cin, int Np,
                const float* Wq, const float* Wk, const float* Wv, const float* Wo,
                const float* Wf1, const float* Wf2, float* out)
{
    long rows = (long)BATCH * Np;
    float cntInv = 1.f / (float)rows;
    // knn on X
    rowsumsq_kernel<<<(unsigned)((rows + 255) / 256), 256>>>(X, ldx, cin, rows, P.sq);
    gemm(X, X, P.S, 0, Np, Np, cin, ldx, ldx, Np, 0,
         (long)Np * ldx, (long)Np * ldx, (long)Np * Np, 0, 1, BATCH, 0);
    knn_select_kernel<<<dim3(Np, BATCH), 128>>>(P.S, P.sq, Np, P.idx);
    // q,k,v
    gemm(X, Wq, P.q, 0, (int)rows, 128, cin, ldx, cin, 128, 0, 0, 0, 0, 0, 1, 1, 0);
    gemm(X, Wk, P.k, 0, (int)rows, 128, cin, ldx, cin, 128, 0, 0, 0, 0, 0, 1, 1, 0);
    gemm(X, Wv, P.v, 0, (int)rows, 128, cin, ldx, cin, 128, 0, 0, 0, 0, 0, 1, 1, 0);
    attn_kernel<<<dim3(Np, BATCH), 128>>>(P.q, P.k, P.v, P.idx, P.o, Np);
    // y = leaky(bn(Wo@out))
    gemm(P.o, Wo, P.ff, 0, (int)rows, 128, 128, 128, 128, 128, 0, 0, 0, 0, 0, 1, 1, 0);
    bnstats(P.ff, 128, rows, 128, cntInv, P.ps, P.pq, P.mu, P.is);
    bnleaky(P.ff, 128, P.y, 128, 0, 0, P.mu, P.is, rows, 128);
    // f1 = leaky(bn(Wf1@y))
    gemm(P.y, Wf1, P.f1, 0, (int)rows, 512, 128, 128, 128, 512, 0, 0, 0, 0, 0, 1, 1, 0);
    bnstats(P.f1, 512, rows, 512, cntInv, P.ps, P.pq, P.mu, P.is);
    bnleaky(P.f1, 512, P.f1, 512, 0, 0, P.mu, P.is, rows, 512);
    // out = y + leaky(bn(Wf2@f1))
    gemm(P.f1, Wf2, P.ff, 0, (int)rows, 128, 512, 512, 512, 128, 0, 0, 0, 0, 0, 1, 1, 0);
    bnstats(P.ff, 128, rows, 128, cntInv, P.ps, P.pq, P.mu, P.is);
    bnleaky(P.ff, 128, out, 128, P.y, 128, P.mu, P.is, rows, 128);
}

extern "C" void kernel_launch(void* const* d_in, const int* in_sizes, int n_in,
                              void* d_out, int out_size)
{
    Ptrs P;
    cudaGetSymbolAddress((void**)&P.S, d_S);   cudaGetSymbolAddress((void**)&P.xp, d_xp);
    cudaGetSymbolAddress((void**)&P.sq, d_sq); cudaGetSymbolAddress((void**)&P.idx, d_idx);
    cudaGetSymbolAddress((void**)&P.A, d_A);   cudaGetSymbolAddress((void**)&P.Bm, d_Bm);
    cudaGetSymbolAddress((void**)&P.h, d_h);   cudaGetSymbolAddress((void**)&P.q, d_q);
    cudaGetSymbolAddress((void**)&P.k, d_k);   cudaGetSymbolAddress((void**)&P.v, d_v);
    cudaGetSymbolAddress((void**)&P.o, d_o);   cudaGetSymbolAddress((void**)&P.y, d_y);
    cudaGetSymbolAddress((void**)&P.f1, d_f1); cudaGetSymbolAddress((void**)&P.ff, d_ff);
    cudaGetSymbolAddress((void**)&P.hf, d_hf); cudaGetSymbolAddress((void**)&P.hd, d_hd);
    cudaGetSymbolAddress((void**)&P.hd2, d_hd2); cudaGetSymbolAddress((void**)&P.hu, d_hu);
    cudaGetSymbolAddress((void**)&P.xt, d_xt); cudaGetSymbolAddress((void**)&P.xh, d_xh);
    cudaGetSymbolAddress((void**)&P.xc, d_xc); cudaGetSymbolAddress((void**)&P.x3, d_x3);
    cudaGetSymbolAddress((void**)&P.ot, d_ot); cudaGetSymbolAddress((void**)&P.ps, d_ps);
    cudaGetSymbolAddress((void**)&P.pq, d_pq); cudaGetSymbolAddress((void**)&P.mu, d_mu);
    cudaGetSymbolAddress((void**)&P.is, d_is); cudaGetSymbolAddress((void**)&P.wd, d_wd);
    cudaGetSymbolAddress((void**)&P.rm, d_rm); cudaGetSymbolAddress((void**)&P.ri, d_ri);
    cudaGetSymbolAddress((void**)&P.sc, d_sc); cudaGetSymbolAddress((void**)&P.sel, d_sel);
    cudaGetSymbolAddress((void**)&P.g, d_g);   cudaGetSymbolAddress((void**)&P.gc, d_gc);
    cudaGetSymbolAddress((void**)&P.cid, d_cid);

    const float* x    = (const float*)d_in[0];
    const float* cat  = (const float*)d_in[1];
    const float* We0  = (const float*)d_in[2];
    const float* We1  = (const float*)d_in[3];
    const float* Wq0  = (const float*)d_in[4];
    const float* Wk0  = (const float*)d_in[5];
    const float* Wv0  = (const float*)d_in[6];
    const float* Wo0  = (const float*)d_in[7];
    const float* Wf10 = (const float*)d_in[8];
    const float* Wf20 = (const float*)d_in[9];
    const float* Wq1  = (const float*)d_in[10];
    const float* Wk1  = (const float*)d_in[11];
    const float* Wv1  = (const float*)d_in[12];
    const float* Wo1  = (const float*)d_in[13];
    const float* Wf11 = (const float*)d_in[14];
    const float* Wf21 = (const float*)d_in[15];
    const float* Wq2  = (const float*)d_in[16];
    const float* Wk2  = (const float*)d_in[17];
    const float* Wv2  = (const float*)d_in[18];
    const float* Wo2  = (const float*)d_in[19];
    const float* Wf12 = (const float*)d_in[20];
    const float* Wf22 = (const float*)d_in[21];
    const float* Wdq  = (const float*)d_in[22];
    const float* Wdk  = (const float*)d_in[23];
    const float* Wuq  = (const float*)d_in[24];
    const float* Wuk  = (const float*)d_in[25];
    const float* Wuv  = (const float*)d_in[26];
    const float* Wc   = (const float*)d_in[27];
    const float* Wc1  = (const float*)d_in[28];
    const float* Wc2  = (const float*)d_in[29];
    const float* Wc3  = (const float*)d_in[30];
    const float* Wc4  = (const float*)d_in[31];
    float* out = (float*)d_out;

    const long R16 = (long)BATCH * NPTS;     // 16384
    const long R8  = (long)BATCH * MPTS;     // 8192

    // -------- input transpose --------
    tin_kernel<<<(BATCH * NPTS * 3 + 255) / 256, 256>>>(x, P.xp);

    // -------- edge conv 1 (3ch -> 128) --------
    wdiff_kernel<<<(128 * 3 + 255) / 256, 256>>>(We0, P.wd, 128, 3, 6);
    gemm(P.xp, P.wd, P.A, 0, (int)R16, 128, 3, 3, 3, 128, 0, 0, 0, 0, 0, 1, 1, 0);
    gemm(P.xp, We0 + 3, P.Bm, 0, (int)R16, 128, 3, 3, 6, 128, 0, 0, 0, 0, 0, 1, 1, 0);
    rowsumsq_kernel<<<(unsigned)((R16 + 255) / 256), 256>>>(P.xp, 3, 3, R16, P.sq);
    gemm(P.xp, P.xp, P.S, 0, NPTS, NPTS, 3, 3, 3, NPTS,
         0, (long)NPTS * 3, (long)NPTS * 3, (long)NPTS * NPTS, 0, 1, BATCH, 0);
    knn_select_kernel<<<dim3(NPTS, BATCH), 128>>>(P.S, P.sq, NPTS, P.idx);
    edge_gather_kernel<<<dim3(NPTS, BATCH), 128>>>(P.A, P.Bm, P.idx, P.h, 256, P.ps, P.pq, NPTS);
    reduce_stats_kernel<<<128, 256>>>(P.ps, P.pq, (int)R16, 128, 1.f / (float)(R16 * KNN), P.mu, P.is);
    bnleaky(P.h, 256, P.h, 256, 0, 0, P.mu, P.is, R16, 128);

    // -------- edge conv 2 (e0:128 -> 128, written to h[:,128:256]) --------
    wdiff_kernel<<<(128 * 128 + 255) / 256, 256>>>(We1, P.wd, 128, 128, 256);
    gemm(P.h, P.wd, P.A, 0, (int)R16, 128, 128, 256, 128, 128, 0, 0, 0, 0, 0, 1, 1, 0);
    gemm(P.h, We1 + 128, P.Bm, 0, (int)R16, 128, 128, 256, 256, 128, 0, 0, 0, 0, 0, 1, 1, 0);
    rowsumsq_kernel<<<(unsigned)((R16 + 255) / 256), 256>>>(P.h, 256, 128, R16, P.sq);
    gemm(P.h, P.h, P.S, 0, NPTS, NPTS, 128, 256, 256, NPTS,
         0, (long)NPTS * 256, (long)NPTS * 256, (long)NPTS * NPTS, 0, 1, BATCH, 0);
    knn_select_kernel<<<dim3(NPTS, BATCH), 128>>>(P.S, P.sq, NPTS, P.idx);
    edge_gather_kernel<<<dim3(NPTS, BATCH), 128>>>(P.A, P.Bm, P.idx, P.h + 128, 256, P.ps, P.pq, NPTS);
    reduce_stats_kernel<<<128, 256>>>(P.ps, P.pq, (int)R16, 128, 1.f / (float)(R16 * KNN), P.mu, P.is);
    bnleaky(P.h + 128, 256, P.h + 128, 256, 0, 0, P.mu, P.is, R16, 128);

    // -------- n2p layer 0 on h (256ch) -> h_full --------
    n2p(P, P.h, 256, 256, NPTS, Wq0, Wk0, Wv0, Wo0, Wf10, Wf20, P.hf);

    // -------- down_global --------
    gemm(P.hf, Wdq, P.q, 0, (int)R16, 128, 128, 128, 128, 128, 0, 0, 0, 0, 0, 1, 1, 0);
    gemm(P.hf, Wdk, P.k, 0, (int)R16, 128, 128, 128, 128, 128, 0, 0, 0, 0, 0, 1, 1, 0);
    gemm(P.q, P.k, P.S, 0, NPTS, NPTS, 128, 128, 128, NPTS,
         0, (long)NPTS * 128, (long)NPTS * 128, (long)NPTS * NPTS, 0, 1, BATCH, 0);
    rowstats_kernel<<<dim3(NPTS, BATCH), 256>>>(P.S, NPTS, P.rm, P.ri);
    colscore_kernel<<<dim3(NPTS / 128, BATCH), 128>>>(P.S, NPTS, P.rm, P.ri, P.sc);
    topm_kernel<<<BATCH, 1024>>>(P.sc, P.sel);
    gather_rows_kernel<<<dim3(MPTS, BATCH), 128>>>(P.hf, P.sel, P.hd);

    // -------- n2p layer 1 on hd (1024 pts) --------
    n2p(P, P.hd, 128, 128, MPTS, Wq1, Wk1, Wv1, Wo1, Wf11, Wf21, P.hd2);

    // -------- up_cross(hf, hd2) --------
    gemm(P.hf, Wuq, P.q, 0, (int)R16, 128, 128, 128, 128, 128, 0, 0, 0, 0, 0, 1, 1, 0);
    gemm(P.hd2, Wuk, P.k, 0, (int)R8, 128, 128, 128, 128, 128, 0, 0, 0, 0, 0, 1, 1, 0);
    gemm(P.hd2, Wuv, P.v, 0, (int)R8, 128, 128, 128, 128, 128, 0, 0, 0, 0, 0, 1, 1, 0);
    gemm(P.q, P.k, P.S, 0, NPTS, MPTS, 128, 128, 128, MPTS,
         0, (long)NPTS * 128, (long)MPTS * 128, (long)NPTS * MPTS, 0, 1, BATCH, 0);
    row_softmax_kernel<<<(unsigned)R16, 256>>>(P.S, MPTS, ASCALE);
    gemm(P.S, P.v, P.hu, P.hf, NPTS, 128, MPTS, MPTS, 128, 128, 128,
         (long)NPTS * MPTS, (long)MPTS * 128, (long)NPTS * 128, (long)NPTS * 128, 0, BATCH, 1);

    // -------- n2p layer 2 on hu -> x_tmp --------
    n2p(P, P.hu, 128, 128, NPTS, Wq2, Wk2, Wv2, Wo2, Wf12, Wf22, P.xt);

    // -------- head --------
    // cid = leaky(bn(Wc1@category_id))
    gemm(cat, Wc1, P.cid, 0, BATCH, 64, 16, 16, 16, 64, 0, 0, 0, 0, 0, 1, 1, 0);
    bnstats(P.cid, 64, BATCH, 64, 1.f / (float)BATCH, P.ps, P.pq, P.mu, P.is);
    bnleaky(P.cid, 64, P.cid, 64, 0, 0, P.mu, P.is, BATCH, 64);
    // xh = Wc@x_tmp (pre-bn); fused bn+leaky inside max/mean reduction
    gemm(P.xt, Wc, P.xh, 0, (int)R16, 1024, 128, 128, 128, 1024, 0, 0, 0, 0, 0, 1, 1, 0);
    bnstats(P.xh, 1024, R16, 1024, 1.f / (float)R16, P.ps, P.pq, P.mu, P.is);
    gmaxmean_kernel<<<dim3(BATCH, 4), 256>>>(P.xh, P.mu, P.is, P.g);
    cidcopy_kernel<<<BATCH, 64>>>(P.cid, P.g);
    // gvec[b] = Wc2[:, :2112] @ g[b]
    gvec_kernel<<<dim3(8, BATCH), 128>>>(Wc2, P.g, P.gc);
    // xc = leaky(bn(gvec + Wc2[:,2112:]@x_tmp))
    gemm(P.xt, Wc2 + 2112, P.xc, P.gc, (int)R16, 1024, 128, 128, 2240, 1024, 1024,
         0, 0, 0, 0, 1, 1, 2);
    bnstats(P.xc, 1024, R16, 1024, 1.f / (float)R16, P.ps, P.pq, P.mu, P.is);
    bnleaky(P.xc, 1024, P.xc, 1024, 0, 0, P.mu, P.is, R16, 1024);
    // xc3 = leaky(bn(Wc3@xc))
    gemm(P.xc, Wc3, P.x3, 0, (int)R16, 256, 1024, 1024, 1024, 256, 0, 0, 0, 0, 0, 1, 1, 0);
    bnstats(P.x3, 256, R16, 256, 1.f / (float)R16, P.ps, P.pq, P.mu, P.is);
    bnleaky(P.x3, 256, P.x3, 256, 0, 0, P.mu, P.is, R16, 256);
    // out = Wc4@xc3
    gemm(P.x3, Wc4, P.ot, 0, (int)R16, 50, 256, 256, 256, 50, 0, 0, 0, 0, 0, 1, 1, 0);
    tout_kernel<<<(BATCH * 50 * NPTS + 255) / 256, 256>>>(P.ot, out);
}